// round 1
// baseline (speedup 1.0000x reference)
#include <cuda_runtime.h>
#include <stdint.h>

#define NTHREADS 1024
#define HBITS 13
#define NBINS (1 << HBITS)
#define BPT (NBINS / NTHREADS)      // bins per thread = 8
#define CAP 2048                    // candidate buffer per row
#define NEED 1024                   // must cover top-k (<=1023) and top-20
#define MAXB 1024
#define SAMPLING_EPS 1e-5f

// ---------------- scratch (per-row stats) ----------------
__device__ float    g_rmax[MAXB];
__device__ float    g_logZ[MAXB];
__device__ unsigned g_thr[MAXB];

// order-preserving float -> uint32 map (and inverse)
__device__ __forceinline__ unsigned mono(float f) {
    unsigned u = __float_as_uint(f);
    return u ^ ((unsigned)(((int)u) >> 31) | 0x80000000u);
}
__device__ __forceinline__ float inv_mono(unsigned m) {
    unsigned u = (m & 0x80000000u) ? (m ^ 0x80000000u) : ~m;
    return __uint_as_float(u);
}

// ======================================================================
// Kernel 1: per row — online max + logsumexp + 13-bit-key histogram,
// then suffix-scan histogram to find candidate threshold (>= NEED cands).
// ======================================================================
__global__ __launch_bounds__(NTHREADS) void k1_stats(const float* __restrict__ logits, int V) {
    const int row = blockIdx.x;
    const int t = threadIdx.x;
    const float* __restrict__ x = logits + (size_t)row * V;

    __shared__ unsigned hist[NBINS];
    __shared__ unsigned tot[NTHREADS];
    __shared__ float wm[32], ws[32];
    __shared__ unsigned s_bin;

    for (int i = t; i < NBINS; i += NTHREADS) hist[i] = 0u;
    if (t == 0) s_bin = 0u;
    __syncthreads();

    const float NEG_INF = __int_as_float(0xff800000);
    float m = NEG_INF, s = 0.f;

    const int V4 = V >> 2;
    const float4* __restrict__ x4 = (const float4*)x;
    for (int i = t; i < V4; i += NTHREADS) {
        float4 v4 = x4[i];
        float vv[4] = {v4.x, v4.y, v4.z, v4.w};
#pragma unroll
        for (int j = 0; j < 4; j++) {
            float v = vv[j];
            atomicAdd(&hist[mono(v) >> (32 - HBITS)], 1u);
            if (v > m) { s = s * __expf(m - v) + 1.f; m = v; }
            else if (v == m) { s += 1.f; }
            else { s += __expf(v - m); }
        }
    }
    for (int i = (V4 << 2) + t; i < V; i += NTHREADS) {
        float v = x[i];
        atomicAdd(&hist[mono(v) >> (32 - HBITS)], 1u);
        if (v > m) { s = s * __expf(m - v) + 1.f; m = v; }
        else if (v == m) { s += 1.f; }
        else { s += __expf(v - m); }
    }

    // warp reduce (m, s)
#pragma unroll
    for (int off = 16; off; off >>= 1) {
        float om = __shfl_down_sync(0xFFFFFFFFu, m, off);
        float os = __shfl_down_sync(0xFFFFFFFFu, s, off);
        if (om > m) { s = os + s * __expf(m - om); m = om; }
        else if (om == m) { s += os; }
        else { s += os * __expf(om - m); }
    }
    if ((t & 31) == 0) { wm[t >> 5] = m; ws[t >> 5] = s; }
    __syncthreads();  // also makes hist complete for the scan below

    if (t < 32) {
        m = wm[t]; s = ws[t];
#pragma unroll
        for (int off = 16; off; off >>= 1) {
            float om = __shfl_down_sync(0xFFFFFFFFu, m, off);
            float os = __shfl_down_sync(0xFFFFFFFFu, s, off);
            if (om > m) { s = os + s * __expf(m - om); m = om; }
            else if (om == m) { s += os; }
            else { s += os * __expf(om - m); }
        }
        if (t == 0) {
            g_rmax[row] = m;
            g_logZ[row] = m + logf(s);
        }
    }

    // ---- histogram suffix scan: find largest bin b with suffix(b) >= NEED ----
    unsigned csum = 0;
#pragma unroll
    for (int b = 0; b < BPT; b++) csum += hist[t * BPT + b];
    tot[t] = csum;
    __syncthreads();
    // inclusive suffix scan over thread-chunk totals
    for (int off = 1; off < NTHREADS; off <<= 1) {
        unsigned xv = (t + off < NTHREADS) ? tot[t + off] : 0u;
        __syncthreads();
        tot[t] += xv;
        __syncthreads();
    }
    unsigned above = tot[t] - csum;  // sum of all chunks strictly above mine
    unsigned acc = above, prev = above;
#pragma unroll
    for (int b = BPT - 1; b >= 0; b--) {
        int bin = t * BPT + b;
        acc += hist[bin];            // = suffix(bin)
        if (acc >= NEED && prev < NEED) s_bin = (unsigned)bin;  // unique crossing
        prev = acc;
    }
    __syncthreads();
    if (t == 0) g_thr[row] = (s_bin << (32 - HBITS));
}

// ======================================================================
// Kernel 2: per row — collect candidates (L2-resident second pass),
// bitonic sort, min-p / top-k / top-p, race sampling, top-20, rank, write.
// ======================================================================
__global__ __launch_bounds__(NTHREADS) void k2_sample(
    const float* __restrict__ logits,
    const float* __restrict__ temperature,
    const float* __restrict__ min_p,
    const int*   __restrict__ top_k,
    const float* __restrict__ top_p,
    const float* __restrict__ q,
    float* __restrict__ out,
    int B, int V, int C)
{
    const int row = blockIdx.x;
    const int t = threadIdx.x;

    __shared__ unsigned long long key[CAP];   // (mono(val)<<32) | ~idx
    __shared__ float e[CAP];
    __shared__ float hd[CAP];
    __shared__ float fscan[NTHREADS];
    __shared__ float wsc[32];
    __shared__ int widx[32], wrr[32];
    __shared__ int s_cnt, s_m, s_S, s_rank, s_sampled, s_rstar;

    if (t == 0) { s_cnt = 0; s_m = 0; s_S = 0; s_rank = 0; }
    __syncthreads();

    const unsigned thr = g_thr[row];
    const float* __restrict__ x = logits + (size_t)row * V;
    const int V4 = V >> 2;
    const float4* __restrict__ x4 = (const float4*)x;

    // -------- collect candidates --------
    for (int i = t; i < V4; i += NTHREADS) {
        float4 v4 = x4[i];
        float vv[4] = {v4.x, v4.y, v4.z, v4.w};
#pragma unroll
        for (int j = 0; j < 4; j++) {
            unsigned u = mono(vv[j]);
            if (u >= thr) {
                int p = atomicAdd(&s_cnt, 1);
                if (p < CAP)
                    key[p] = ((unsigned long long)u << 32) | (unsigned)(~(unsigned)(4 * i + j));
            }
        }
    }
    for (int i = (V4 << 2) + t; i < V; i += NTHREADS) {
        unsigned u = mono(x[i]);
        if (u >= thr) {
            int p = atomicAdd(&s_cnt, 1);
            if (p < CAP)
                key[p] = ((unsigned long long)u << 32) | (unsigned)(~(unsigned)i);
        }
    }
    __syncthreads();
    const int n = min(s_cnt, CAP);
    for (int i = t; i < CAP; i += NTHREADS)
        if (i >= n) key[i] = 0ULL;   // sentinel sorts to the bottom
    __syncthreads();

    // -------- bitonic sort ascending (keys unique -> reversed = descending) ---
    for (int kk = 2; kk <= CAP; kk <<= 1) {
        for (int j = kk >> 1; j > 0; j >>= 1) {
#pragma unroll
            for (int w = 0; w < CAP / NTHREADS; w++) {
                int i = t + w * NTHREADS;
                int l = i ^ j;
                if (l > i) {
                    unsigned long long a = key[i], b = key[l];
                    bool sw = ((i & kk) == 0) ? (a > b) : (a < b);
                    if (sw) { key[i] = b; key[l] = a; }
                }
            }
            __syncthreads();
        }
    }

#define DKEY(r) (key[CAP - 1 - (r)])
#define DVAL(r) inv_mono((unsigned)(DKEY(r) >> 32))
#define DIDX(r) ((int)(~(unsigned)DKEY(r)))

    // -------- per-row scalars --------
    const float temp = temperature[row];
    const float mp   = min_p[row];
    const float tp   = top_p[row];
    int kk_ = top_k[row];
    kk_ = max(1, min(kk_, V));
    const float rmax = g_rmax[row];
    const float lZ   = g_logZ[row];
    const float t_mp = rmax + temp * logf(mp);   // min-p threshold in logit space

    // -------- m = # min-p survivors among candidates --------
    for (int r = t; r < n; r += NTHREADS)
        if (DVAL(r) >= t_mp) atomicAdd(&s_m, 1);
    __syncthreads();
    const int mcnt = s_m;

    // -------- S = # survivors after top-k --------
    if (mcnt >= kk_) {
        float kth = DVAL(kk_ - 1);
        for (int r = t; r < n; r += NTHREADS)
            if (DVAL(r) >= kth) atomicAdd(&s_S, 1);
    }
    __syncthreads();
    const int S = (mcnt >= kk_) ? min(s_S, CAP) : mcnt;

    const bool greedy = (temp < SAMPLING_EPS);
    int sampled, rstar;

    if (!greedy) {
        // -------- softmax numerators over survivors --------
        const float lt0 = DVAL(0) / temp;
        for (int r = t; r < CAP; r += NTHREADS) {
            float ev = 0.f;
            if (r < S) ev = expf(DVAL(r) / temp - lt0);
            e[r] = ev;
        }
        __syncthreads();

        // -------- exclusive prefix sums (head of descending order) --------
        float a0 = e[2 * t], a1 = e[2 * t + 1];
        float tsum = a0 + a1;
        fscan[t] = tsum;
        __syncthreads();
        for (int off = 1; off < NTHREADS; off <<= 1) {
            float xv = (t >= off) ? fscan[t - off] : 0.f;
            __syncthreads();
            fscan[t] += xv;
            __syncthreads();
        }
        const float Z = fscan[NTHREADS - 1];
        float excl = fscan[t] - tsum;
        hd[2 * t]     = excl;
        hd[2 * t + 1] = excl + a0;
        __syncthreads();

        // -------- top-p keep predicate + exponential race argmax --------
        const float c1 = (1.f - tp) * Z;   // keep r iff (Z - hd[r]) > c1  (csum_asc > 1-top_p)
        const float* __restrict__ qrow = q + (size_t)row * V;
        float best = -1.f;
        int bidx = 0x7FFFFFFF, brr = 0;
        for (int r = t; r < S; r += NTHREADS) {
            if (r == 0 || (Z - hd[r]) > c1) {
                int id = DIDX(r);
                float qv = qrow[id];
                float ex = -logf(fmaxf(qv, 1e-10f));
                float sc = e[r] / ex;
                if (sc > best || (sc == best && id < bidx)) { best = sc; bidx = id; brr = r; }
            }
        }
#pragma unroll
        for (int off = 16; off; off >>= 1) {
            float ob = __shfl_down_sync(0xFFFFFFFFu, best, off);
            int   oi = __shfl_down_sync(0xFFFFFFFFu, bidx, off);
            int   orr = __shfl_down_sync(0xFFFFFFFFu, brr, off);
            if (ob > best || (ob == best && oi < bidx)) { best = ob; bidx = oi; brr = orr; }
        }
        if ((t & 31) == 0) { wsc[t >> 5] = best; widx[t >> 5] = bidx; wrr[t >> 5] = brr; }
        __syncthreads();
        if (t < 32) {
            best = wsc[t]; bidx = widx[t]; brr = wrr[t];
#pragma unroll
            for (int off = 16; off; off >>= 1) {
                float ob = __shfl_down_sync(0xFFFFFFFFu, best, off);
                int   oi = __shfl_down_sync(0xFFFFFFFFu, bidx, off);
                int   orr = __shfl_down_sync(0xFFFFFFFFu, brr, off);
                if (ob > best || (ob == best && oi < bidx)) { best = ob; bidx = oi; brr = orr; }
            }
            if (t == 0) { s_sampled = bidx; s_rstar = brr; }
        }
        __syncthreads();
        sampled = s_sampled;
        rstar = s_rstar;
    } else {
        sampled = DIDX(0);   // greedy = argmax (min index on ties)
        rstar = 0;
    }

    // -------- rank: count logprob(val) >= logprob(sampled) over candidates ----
    const float vstar = DVAL(rstar);
    const float tlp = vstar - lZ;
    for (int r = t; r < n; r += NTHREADS) {
        if ((DVAL(r) - lZ) >= tlp) atomicAdd(&s_rank, 1);
    }
    __syncthreads();

    // -------- outputs: [sampled(B)] [out_idx(B*C)] [out_lp(B*C)] [ranks(B)] ---
    if (t == 0) {
        out[row] = (float)sampled;
        out[(size_t)B + (size_t)row * C] = (float)sampled;
        out[(size_t)B + (size_t)B * C + (size_t)row * C] = tlp;
        out[(size_t)B + 2 * (size_t)B * C + row] = (float)s_rank;
    }
    if (t >= 1 && t < C) {
        int r = t - 1;   // top-(C-1) entries
        unsigned long long kv = DKEY(r);
        out[(size_t)B + (size_t)row * C + t] = (float)(~(unsigned)kv);
        out[(size_t)B + (size_t)B * C + (size_t)row * C + t] = inv_mono((unsigned)(kv >> 32)) - lZ;
    }
#undef DKEY
#undef DVAL
#undef DIDX
}

// ======================================================================
extern "C" void kernel_launch(void* const* d_in, const int* in_sizes, int n_in,
                              void* d_out, int out_size) {
    const float* logits      = (const float*)d_in[0];
    const float* temperature = (const float*)d_in[1];
    const float* min_p       = (const float*)d_in[2];
    const int*   top_k       = (const int*)d_in[3];
    const float* top_p       = (const float*)d_in[4];
    const float* q           = (const float*)d_in[5];

    int B = in_sizes[1];
    int V = in_sizes[0] / B;
    int C = (out_size / B - 2) / 2;   // num_logprobs + 1

    k1_stats<<<B, NTHREADS>>>(logits, V);
    k2_sample<<<B, NTHREADS>>>(logits, temperature, min_p, top_k, top_p, q,
                               (float*)d_out, B, V, C);
}

// round 3
// speedup vs baseline: 1.2115x; 1.2115x over previous
#include <cuda_runtime.h>
#include <stdint.h>

#define NTHREADS 1024
#define NWARPS (NTHREADS / 32)
#define HBITS 13
#define NBINS (1 << HBITS)
#define BPT (NBINS / NTHREADS)      // bins per thread = 8
#define CAP 2048                    // candidate buffer per row
#define NEED 1024                   // must cover top-k (<=1023) and top-20
#define SAMPLING_EPS 1e-5f

// order-preserving float -> uint32 map (and inverse)
__device__ __forceinline__ unsigned mono(float f) {
    unsigned u = __float_as_uint(f);
    return u ^ ((unsigned)(((int)u) >> 31) | 0x80000000u);
}
__device__ __forceinline__ float inv_mono(unsigned m) {
    unsigned u = (m & 0x80000000u) ? (m ^ 0x80000000u) : ~m;
    return __uint_as_float(u);
}

// ======================================================================
// Single fused kernel: per row (1 CTA):
//   pass A (DRAM): max + 13-bit histogram
//   shuffle scans -> candidate threshold
//   pass B (L2-hot, same CTA): sum-exp + candidate collection into smem
//   bitonic sort, min-p / top-k / top-p, race sampling, top-20, rank
// ======================================================================
__global__ __launch_bounds__(NTHREADS, 1) void sampler_fused(
    const float* __restrict__ logits,
    const float* __restrict__ temperature,
    const float* __restrict__ min_p,
    const int*   __restrict__ top_k,
    const float* __restrict__ top_p,
    const float* __restrict__ q,
    float* __restrict__ out,
    int B, int V, int C)
{
    const int row = blockIdx.x;
    const int t = threadIdx.x;
    const int lane = t & 31, warp = t >> 5;

    // 32KB buffer: phase A = hist[8192 u32]; phase B+ = key[2048 u64] | e[2048 f32] | hd[2048 f32]
    __shared__ __align__(16) unsigned char sbuf[NBINS * 4];
    __shared__ float wf[NWARPS];
    __shared__ unsigned wu[NWARPS];
    __shared__ int wi[NWARPS], wr[NWARPS];
    __shared__ unsigned s_bin;
    __shared__ int s_cnt, s_m, s_S, s_rank, s_sampled, s_rstar;
    __shared__ float s_stat[2];   // [0]=rmax [1]=logZ

    unsigned* hist = (unsigned*)sbuf;

    if (t == 0) { s_cnt = 0; s_m = 0; s_S = 0; s_rank = 0; s_bin = 0; }
#pragma unroll
    for (int z = t; z < NBINS; z += NTHREADS) hist[z] = 0u;
    __syncthreads();

    const float* __restrict__ x = logits + (size_t)row * V;
    const int V4 = V >> 2;
    const float4* __restrict__ x4 = (const float4*)x;
    const float NEG_INF = __int_as_float(0xff800000);

    // ---------------- pass A: max + histogram (DRAM streaming) ----------------
    float m0 = NEG_INF, m1 = NEG_INF, m2 = NEG_INF, m3 = NEG_INF;
    auto procA = [&](float4 v) {
        atomicAdd(&hist[mono(v.x) >> (32 - HBITS)], 1u);
        atomicAdd(&hist[mono(v.y) >> (32 - HBITS)], 1u);
        atomicAdd(&hist[mono(v.z) >> (32 - HBITS)], 1u);
        atomicAdd(&hist[mono(v.w) >> (32 - HBITS)], 1u);
        m0 = fmaxf(m0, v.x); m1 = fmaxf(m1, v.y);
        m2 = fmaxf(m2, v.z); m3 = fmaxf(m3, v.w);
    };
    int i = t;
    for (; i + 3 * NTHREADS < V4; i += 4 * NTHREADS) {
        float4 a = x4[i];
        float4 b = x4[i + NTHREADS];
        float4 c = x4[i + 2 * NTHREADS];
        float4 d = x4[i + 3 * NTHREADS];
        procA(a); procA(b); procA(c); procA(d);
    }
    for (; i < V4; i += NTHREADS) procA(x4[i]);
    for (int j = (V4 << 2) + t; j < V; j += NTHREADS) {
        float v = x[j];
        atomicAdd(&hist[mono(v) >> (32 - HBITS)], 1u);
        m0 = fmaxf(m0, v);
    }

    // block max reduce
    float m = fmaxf(fmaxf(m0, m1), fmaxf(m2, m3));
#pragma unroll
    for (int off = 16; off; off >>= 1)
        m = fmaxf(m, __shfl_xor_sync(0xFFFFFFFFu, m, off));
    if (lane == 0) wf[warp] = m;
    __syncthreads();                       // hist complete + wf visible
    if (warp == 0) {
        float mm = wf[lane];
#pragma unroll
        for (int off = 16; off; off >>= 1)
            mm = fmaxf(mm, __shfl_xor_sync(0xFFFFFFFFu, mm, off));
        if (lane == 0) s_stat[0] = mm;
    }

    // ---------------- threshold from histogram (shuffle suffix scan) ----------
    unsigned csum = 0;
#pragma unroll
    for (int b = 0; b < BPT; b++) csum += hist[t * BPT + b];
    unsigned iv = csum;
#pragma unroll
    for (int off = 1; off < 32; off <<= 1) {
        unsigned nb = __shfl_up_sync(0xFFFFFFFFu, iv, off);
        if (lane >= off) iv += nb;
    }
    if (lane == 31) wu[warp] = iv;
    __syncthreads();                       // also publishes s_stat[0]
    if (warp == 0) {
        unsigned wv = wu[lane];
#pragma unroll
        for (int off = 1; off < 32; off <<= 1) {
            unsigned nb = __shfl_up_sync(0xFFFFFFFFu, wv, off);
            if (lane >= off) wv += nb;
        }
        wu[lane] = wv;
    }
    __syncthreads();
    unsigned incl = iv + (warp ? wu[warp - 1] : 0u);
    unsigned Total = wu[NWARPS - 1];
    unsigned above = Total - incl;         // sum of chunks strictly above mine
    unsigned acc = above, prev = above;
#pragma unroll
    for (int b = BPT - 1; b >= 0; b--) {
        int bin = t * BPT + b;
        acc += hist[bin];                  // = suffix(bin)
        if (acc >= NEED && prev < NEED) s_bin = (unsigned)bin;  // unique crossing
        prev = acc;
    }
    __syncthreads();
    const unsigned thr = s_bin << (32 - HBITS);
    const float rmax = s_stat[0];

    // ---------------- pass B: sum-exp + collect candidates (L2-hot) ----------
    unsigned long long* key = (unsigned long long*)sbuf;       // overwrites hist
    float* e  = (float*)(sbuf + CAP * 8);
    float* hd = (float*)(sbuf + CAP * 8 + CAP * 4);

    float ssum = 0.f;
    auto procB = [&](float4 v, int base) {
        ssum += __expf(v.x - rmax) + __expf(v.y - rmax)
              + __expf(v.z - rmax) + __expf(v.w - rmax);
        unsigned u;
        u = mono(v.x); if (u >= thr) { int p = atomicAdd(&s_cnt, 1); if (p < CAP) key[p] = ((unsigned long long)u << 32) | (unsigned)~(unsigned)(base + 0); }
        u = mono(v.y); if (u >= thr) { int p = atomicAdd(&s_cnt, 1); if (p < CAP) key[p] = ((unsigned long long)u << 32) | (unsigned)~(unsigned)(base + 1); }
        u = mono(v.z); if (u >= thr) { int p = atomicAdd(&s_cnt, 1); if (p < CAP) key[p] = ((unsigned long long)u << 32) | (unsigned)~(unsigned)(base + 2); }
        u = mono(v.w); if (u >= thr) { int p = atomicAdd(&s_cnt, 1); if (p < CAP) key[p] = ((unsigned long long)u << 32) | (unsigned)~(unsigned)(base + 3); }
    };
    i = t;
    for (; i + NTHREADS < V4; i += 2 * NTHREADS) {
        float4 a = x4[i];
        float4 b = x4[i + NTHREADS];
        procB(a, 4 * i);
        procB(b, 4 * (i + NTHREADS));
    }
    for (; i < V4; i += NTHREADS) procB(x4[i], 4 * i);
    for (int j = (V4 << 2) + t; j < V; j += NTHREADS) {
        float v = x[j];
        ssum += __expf(v - rmax);
        unsigned u = mono(v);
        if (u >= thr) { int p = atomicAdd(&s_cnt, 1); if (p < CAP) key[p] = ((unsigned long long)u << 32) | (unsigned)~(unsigned)j; }
    }
#pragma unroll
    for (int off = 16; off; off >>= 1)
        ssum += __shfl_xor_sync(0xFFFFFFFFu, ssum, off);
    if (lane == 0) wf[warp] = ssum;
    __syncthreads();                       // key writes + s_cnt final
    if (t == 0) {
        float stot = 0.f;
#pragma unroll
        for (int w2 = 0; w2 < NWARPS; w2++) stot += wf[w2];
        s_stat[1] = rmax + logf(stot);
    }
    const int n = min(s_cnt, CAP);
    for (int z = n + t; z < CAP; z += NTHREADS) key[z] = 0ULL;  // sentinel
    __syncthreads();
    const float lZ = s_stat[1];

    // ---------------- bitonic sort ascending (unique keys; reversed = desc) ---
    for (int kk = 2; kk <= CAP; kk <<= 1) {
        for (int j = kk >> 1; j > 0; j >>= 1) {
#pragma unroll
            for (int w = 0; w < CAP / NTHREADS; w++) {
                int idx = t + w * NTHREADS;
                int l = idx ^ j;
                if (l > idx) {
                    unsigned long long a = key[idx], b = key[l];
                    bool sw = ((idx & kk) == 0) ? (a > b) : (a < b);
                    if (sw) { key[idx] = b; key[l] = a; }
                }
            }
            __syncthreads();
        }
    }

#define DKEY(r) (key[CAP - 1 - (r)])
#define DVAL(r) inv_mono((unsigned)(DKEY(r) >> 32))
#define DIDX(r) ((int)(~(unsigned)DKEY(r)))

    // ---------------- per-row scalars ----------------
    const float temp = temperature[row];
    const float mp   = min_p[row];
    const float tp   = top_p[row];
    int kk_ = top_k[row];
    kk_ = max(1, min(kk_, V));
    const float t_mp = rmax + temp * logf(mp);   // min-p threshold in logit space

    // m = # min-p survivors among candidates
    for (int r = t; r < n; r += NTHREADS)
        if (DVAL(r) >= t_mp) atomicAdd(&s_m, 1);
    __syncthreads();
    const int mcnt = s_m;

    // S = # survivors after top-k
    if (mcnt >= kk_) {
        float kth = DVAL(kk_ - 1);
        for (int r = t; r < n; r += NTHREADS)
            if (DVAL(r) >= kth) atomicAdd(&s_S, 1);
    }
    __syncthreads();
    const int S = (mcnt >= kk_) ? min(s_S, CAP) : mcnt;

    const bool greedy = (temp < SAMPLING_EPS);
    int sampled, rstar;

    if (!greedy) {
        // softmax numerators over survivors
        const float lt0 = DVAL(0) / temp;
        for (int r = t; r < CAP; r += NTHREADS) {
            float ev = 0.f;
            if (r < S) ev = expf(DVAL(r) / temp - lt0);
            e[r] = ev;
        }
        __syncthreads();

        // exclusive prefix over descending order (shuffle scan)
        float a0 = e[2 * t], a1 = e[2 * t + 1];
        float tsum = a0 + a1;
        float sv = tsum;
#pragma unroll
        for (int off = 1; off < 32; off <<= 1) {
            float nb = __shfl_up_sync(0xFFFFFFFFu, sv, off);
            if (lane >= off) sv += nb;
        }
        if (lane == 31) wf[warp] = sv;
        __syncthreads();
        if (warp == 0) {
            float wv = wf[lane];
#pragma unroll
            for (int off = 1; off < 32; off <<= 1) {
                float nb = __shfl_up_sync(0xFFFFFFFFu, wv, off);
                if (lane >= off) wv += nb;
            }
            wf[lane] = wv;
        }
        __syncthreads();
        float inclf = sv + (warp ? wf[warp - 1] : 0.f);
        const float Z = wf[NWARPS - 1];
        float excl = inclf - tsum;
        hd[2 * t]     = excl;
        hd[2 * t + 1] = excl + a0;
        __syncthreads();

        // top-p keep predicate + exponential race argmax
        const float c1 = (1.f - tp) * Z;   // keep r iff (Z - hd[r]) > c1
        const float* __restrict__ qrow = q + (size_t)row * V;
        float best = -1.f;
        int bidx = 0x7FFFFFFF, brr = 0;
        for (int r = t; r < S; r += NTHREADS) {
            if (r == 0 || (Z - hd[r]) > c1) {
                int id = DIDX(r);
                float qv = qrow[id];
                float ex = -logf(fmaxf(qv, 1e-10f));
                float sc = e[r] / ex;
                if (sc > best || (sc == best && id < bidx)) { best = sc; bidx = id; brr = r; }
            }
        }
#pragma unroll
        for (int off = 16; off; off >>= 1) {
            float ob = __shfl_down_sync(0xFFFFFFFFu, best, off);
            int   oi = __shfl_down_sync(0xFFFFFFFFu, bidx, off);
            int   orr = __shfl_down_sync(0xFFFFFFFFu, brr, off);
            if (ob > best || (ob == best && oi < bidx)) { best = ob; bidx = oi; brr = orr; }
        }
        if (lane == 0) { wf[warp] = best; wi[warp] = bidx; wr[warp] = brr; }
        __syncthreads();
        if (warp == 0) {
            best = wf[lane]; bidx = wi[lane]; brr = wr[lane];
#pragma unroll
            for (int off = 16; off; off >>= 1) {
                float ob = __shfl_down_sync(0xFFFFFFFFu, best, off);
                int   oi = __shfl_down_sync(0xFFFFFFFFu, bidx, off);
                int   orr = __shfl_down_sync(0xFFFFFFFFu, brr, off);
                if (ob > best || (ob == best && oi < bidx)) { best = ob; bidx = oi; brr = orr; }
            }
            if (lane == 0) { s_sampled = bidx; s_rstar = brr; }
        }
        __syncthreads();
        sampled = s_sampled;
        rstar = s_rstar;
    } else {
        sampled = DIDX(0);   // greedy = argmax (min index on ties)
        rstar = 0;
    }

    // rank: count logprob(val) >= logprob(sampled) over candidates
    const float vstar = DVAL(rstar);
    const float tlp = vstar - lZ;
    for (int r = t; r < n; r += NTHREADS) {
        if ((DVAL(r) - lZ) >= tlp) atomicAdd(&s_rank, 1);
    }
    __syncthreads();

    // outputs: [sampled(B)] [out_idx(B*C)] [out_lp(B*C)] [ranks(B)]
    if (t == 0) {
        out[row] = (float)sampled;
        out[(size_t)B + (size_t)row * C] = (float)sampled;
        out[(size_t)B + (size_t)B * C + (size_t)row * C] = tlp;
        out[(size_t)B + 2 * (size_t)B * C + row] = (float)s_rank;
    }
    if (t >= 1 && t < C) {
        int r = t - 1;   // top-(C-1) entries
        unsigned long long kv = DKEY(r);
        out[(size_t)B + (size_t)row * C + t] = (float)(~(unsigned)kv);
        out[(size_t)B + (size_t)B * C + (size_t)row * C + t] = inv_mono((unsigned)(kv >> 32)) - lZ;
    }
#undef DKEY
#undef DVAL
#undef DIDX
}

// ======================================================================
extern "C" void kernel_launch(void* const* d_in, const int* in_sizes, int n_in,
                              void* d_out, int out_size) {
    const float* logits      = (const float*)d_in[0];
    const float* temperature = (const float*)d_in[1];
    const float* min_p       = (const float*)d_in[2];
    const int*   top_k       = (const int*)d_in[3];
    const float* top_p       = (const float*)d_in[4];
    const float* q           = (const float*)d_in[5];

    int B = in_sizes[1];
    int V = in_sizes[0] / B;
    int C = (out_size / B - 2) / 2;   // num_logprobs + 1

    sampler_fused<<<B, NTHREADS>>>(logits, temperature, min_p, top_k, top_p, q,
                                   (float*)d_out, B, V, C);
}